// round 12
// baseline (speedup 1.0000x reference)
#include <cuda_runtime.h>
#include <math.h>

#define NV      65536
#define NV4     (NV*4)
#define ITERS   40
#define NF      130050
#define KSTRIDE 64        // per-RHS scalar row stride -> 16 independent atomic lines
#define CGT     1024      // CG kernel block size (straggler mitigation: low oe)
#define CGB     (NV4/CGT) // 256 blocks

// ---- device scratch (no allocations allowed) ----
__device__ __align__(16) float  g_W[NV*7];      // aggregated COO weights (slot 0 = diag)
__device__ __align__(16) float4 g_w8[NV*2];     // packed per-vertex: {Dw,o0,o1,o2},{o3,o4,o5,Minv}
__device__ __align__(16) float4 g_X[NV4];
__device__ __align__(16) float4 g_R[NV4];
__device__ __align__(16) float4 g_P[NV4];
__device__ __align__(16) float4 g_AP[NV4];
__device__ __align__(16) float4 g_Z[NV4];
// scalar tables: [rhs][k] rows -> 16 independent atomic streams
__device__ __align__(16) float  g_dn[16*KSTRIDE];
__device__ __align__(16) float  g_rz[16*KSTRIDE];

// Block reduce of per-thread float4 (4 RHS of this thread's q-group) into
// 16 per-RHS scalars, atomicAdd to base[rhs*KSTRIDE + k]. blockDim == CGT.
__device__ __forceinline__ void block_reduce16(float4 s, float* base, int k){
    #pragma unroll
    for (int m = 4; m < 32; m <<= 1){
        s.x += __shfl_xor_sync(0xffffffffu, s.x, m);
        s.y += __shfl_xor_sync(0xffffffffu, s.y, m);
        s.z += __shfl_xor_sync(0xffffffffu, s.z, m);
        s.w += __shfl_xor_sync(0xffffffffu, s.w, m);
    }
    __shared__ float sm[CGT/32][16];
    int lane = threadIdx.x & 31, wid = threadIdx.x >> 5;
    if (lane < 4){
        sm[wid][lane*4+0] = s.x;
        sm[wid][lane*4+1] = s.y;
        sm[wid][lane*4+2] = s.z;
        sm[wid][lane*4+3] = s.w;
    }
    __syncthreads();
    if (threadIdx.x < 16){
        float acc = 0.f;
        #pragma unroll
        for (int w = 0; w < CGT/32; w++) acc += sm[w][threadIdx.x];
        atomicAdd(&base[threadIdx.x*KSTRIDE + k], acc);
    }
}

__global__ void zero_k(){
    int tid = blockIdx.x * blockDim.x + threadIdx.x;   // grid sized to exactly NV*7
    g_W[tid] = 0.f;
    if (tid < 16*KSTRIDE){ g_dn[tid] = 0.f; g_rz[tid] = 0.f; }
}

__global__ void scatter_k(const int* __restrict__ row, const int* __restrict__ col,
                          const float* __restrict__ val, int nnz){
    int e = blockIdx.x * blockDim.x + threadIdx.x;
    if (e >= nnz) return;
    int r = row[e];
    int d = col[e] - r;
    int slot;
    if      (d == 0)    slot = 0;
    else if (d == -256) slot = 1;
    else if (d == 256)  slot = 2;
    else if (d == -1)   slot = 3;
    else if (d == 1)    slot = 4;
    else if (d == -257) slot = 5;
    else if (d == 257)  slot = 6;
    else return;
    atomicAdd(&g_W[r*7 + slot], val[e]);
}

// Fold t, pack weights, init CG state (X=0, R=B, Z=Minv*B), reduce rz0.
__global__ void __launch_bounds__(CGT, 1)
init_k(const float* __restrict__ M, const float* __restrict__ B,
       const float* __restrict__ tp){
    int tid = blockIdx.x * CGT + threadIdx.x;   // exactly NV4 threads
    int v = tid >> 2, q = tid & 3;
    float t = *tp;
    float Dw   = M[v] + t * g_W[v*7];
    float Minv = 1.0f / fmaxf(Dw, 1e-12f);
    if (q == 0){
        g_w8[v*2]   = make_float4(Dw, t*g_W[v*7+1], t*g_W[v*7+2], t*g_W[v*7+3]);
        g_w8[v*2+1] = make_float4(t*g_W[v*7+4], t*g_W[v*7+5], t*g_W[v*7+6], Minv);
    }
    float4 r = ((const float4*)B)[tid];
    float4 z = make_float4(Minv*r.x, Minv*r.y, Minv*r.z, Minv*r.w);
    g_X[tid] = make_float4(0.f,0.f,0.f,0.f);
    g_R[tid] = r;
    g_Z[tid] = z;
    block_reduce16(make_float4(r.x*z.x, r.y*z.y, r.z*z.z, r.w*z.w), g_rz, 0);
}

// K1: (k>0) X += alpha_{k-1}*P_old ; beta = rz[k]/rz[k-1] ;
//     P = Z + beta*P ; AP = A*Z + beta*AP ; denom[k] = <P,AP>
__global__ void __launch_bounds__(CGT, 1)
cg_k1(int k){
    int tid = blockIdx.x * CGT + threadIdx.x;
    int v = tid >> 2, q = tid & 3;
    float4 wa = __ldg(&g_w8[v*2]);      // Dw,o0,o1,o2
    float4 wb = __ldg(&g_w8[v*2+1]);    // o3,o4,o5,Minv
    float4 z = __ldg(&g_Z[tid]);
    float4 ap = make_float4(wa.x*z.x, wa.x*z.y, wa.x*z.z, wa.x*z.w);

    const int off[6] = {-256, 256, -1, 1, -257, 257};
    const float wgt[6] = {wa.y, wa.z, wa.w, wb.x, wb.y, wb.z};
    #pragma unroll
    for (int e = 0; e < 6; e++){
        int nb = v + off[e];
        nb = max(0, min(NV-1, nb));       // absent-edge weight is exactly 0
        float4 zn = __ldg(&g_Z[nb*4 + q]);
        float w = wgt[e];
        ap.x = fmaf(w, zn.x, ap.x);
        ap.y = fmaf(w, zn.y, ap.y);
        ap.z = fmaf(w, zn.z, ap.z);
        ap.w = fmaf(w, zn.w, ap.w);
    }
    float4 p;
    if (k == 0){
        p = z;
    } else {
        const int rb = q*4;
        // alpha_{k-1} (identical rounding to K2's) and beta_k from scalar tables
        float4 a, bt;
        a.x  = g_rz[(rb+0)*KSTRIDE + k-1] / fmaxf(g_dn[(rb+0)*KSTRIDE + k-1], 1e-30f);
        a.y  = g_rz[(rb+1)*KSTRIDE + k-1] / fmaxf(g_dn[(rb+1)*KSTRIDE + k-1], 1e-30f);
        a.z  = g_rz[(rb+2)*KSTRIDE + k-1] / fmaxf(g_dn[(rb+2)*KSTRIDE + k-1], 1e-30f);
        a.w  = g_rz[(rb+3)*KSTRIDE + k-1] / fmaxf(g_dn[(rb+3)*KSTRIDE + k-1], 1e-30f);
        bt.x = g_rz[(rb+0)*KSTRIDE + k] / fmaxf(g_rz[(rb+0)*KSTRIDE + k-1], 1e-30f);
        bt.y = g_rz[(rb+1)*KSTRIDE + k] / fmaxf(g_rz[(rb+1)*KSTRIDE + k-1], 1e-30f);
        bt.z = g_rz[(rb+2)*KSTRIDE + k] / fmaxf(g_rz[(rb+2)*KSTRIDE + k-1], 1e-30f);
        bt.w = g_rz[(rb+3)*KSTRIDE + k] / fmaxf(g_rz[(rb+3)*KSTRIDE + k-1], 1e-30f);

        float4 op  = g_P[tid];
        float4 oap = g_AP[tid];
        float4 x   = g_X[tid];
        x.x = fmaf(a.x, op.x, x.x);  x.y = fmaf(a.y, op.y, x.y);
        x.z = fmaf(a.z, op.z, x.z);  x.w = fmaf(a.w, op.w, x.w);
        g_X[tid] = x;
        p.x = fmaf(bt.x, op.x, z.x);  p.y = fmaf(bt.y, op.y, z.y);
        p.z = fmaf(bt.z, op.z, z.z);  p.w = fmaf(bt.w, op.w, z.w);
        ap.x = fmaf(bt.x, oap.x, ap.x);  ap.y = fmaf(bt.y, oap.y, ap.y);
        ap.z = fmaf(bt.z, oap.z, ap.z);  ap.w = fmaf(bt.w, oap.w, ap.w);
    }
    g_P[tid]  = p;
    g_AP[tid] = ap;
    block_reduce16(make_float4(p.x*ap.x, p.y*ap.y, p.z*ap.z, p.w*ap.w), g_dn, k);
}

// K2 (k=0..38): alpha = rz[k]/denom[k] ; R -= alpha*AP ; Z = Minv*R ; rz[k+1] = <R,Z>
__global__ void __launch_bounds__(CGT, 1)
cg_k2(int k){
    int tid = blockIdx.x * CGT + threadIdx.x;
    int v = tid >> 2, q = tid & 3;
    const int rb = q*4;
    float4 a;
    a.x = g_rz[(rb+0)*KSTRIDE + k] / fmaxf(g_dn[(rb+0)*KSTRIDE + k], 1e-30f);
    a.y = g_rz[(rb+1)*KSTRIDE + k] / fmaxf(g_dn[(rb+1)*KSTRIDE + k], 1e-30f);
    a.z = g_rz[(rb+2)*KSTRIDE + k] / fmaxf(g_dn[(rb+2)*KSTRIDE + k], 1e-30f);
    a.w = g_rz[(rb+3)*KSTRIDE + k] / fmaxf(g_dn[(rb+3)*KSTRIDE + k], 1e-30f);

    float4 ap = g_AP[tid];
    float4 r  = g_R[tid];
    r.x = fmaf(-a.x, ap.x, r.x);  r.y = fmaf(-a.y, ap.y, r.y);
    r.z = fmaf(-a.z, ap.z, r.z);  r.w = fmaf(-a.w, ap.w, r.w);
    float minv = __ldg(&g_w8[v*2+1]).w;
    float4 z = make_float4(minv*r.x, minv*r.y, minv*r.z, minv*r.w);
    g_R[tid] = r;
    g_Z[tid] = z;
    block_reduce16(make_float4(r.x*z.x, r.y*z.y, r.z*z.z, r.w*z.w), g_rz, k+1);
}

__device__ __forceinline__ float safe_log_neg(float u){
    float us = u;
    if (isnan(us))      us = 1e-9f;
    else if (isinf(us)) us = (us > 0.f) ? 1.0f : 0.0f;
    return -logf(fmaxf(us, 1e-9f));
}

// Finalize: apply alpha_39, write U and S; then faces Xdir (u recomputed
// on the fly with identical rounding: u = fma(alpha39, p, x)).
__global__ void __launch_bounds__(CGT, 1)
finalize_k(const int* __restrict__ F,
           const float* __restrict__ gI, const float* __restrict__ gJ,
           const float* __restrict__ gK,
           float* __restrict__ outU, float* __restrict__ outX, float* __restrict__ outS){
    int tid = blockIdx.x * CGT + threadIdx.x;
    const int K = ITERS - 1;

    if (tid < NV4){
        int q = tid & 3;
        const int rb = q*4;
        float4 a;
        a.x = g_rz[(rb+0)*KSTRIDE + K] / fmaxf(g_dn[(rb+0)*KSTRIDE + K], 1e-30f);
        a.y = g_rz[(rb+1)*KSTRIDE + K] / fmaxf(g_dn[(rb+1)*KSTRIDE + K], 1e-30f);
        a.z = g_rz[(rb+2)*KSTRIDE + K] / fmaxf(g_dn[(rb+2)*KSTRIDE + K], 1e-30f);
        a.w = g_rz[(rb+3)*KSTRIDE + K] / fmaxf(g_dn[(rb+3)*KSTRIDE + K], 1e-30f);
        float4 p = g_P[tid];
        float4 x = g_X[tid];
        float4 u;
        u.x = fmaf(a.x, p.x, x.x);  u.y = fmaf(a.y, p.y, x.y);
        u.z = fmaf(a.z, p.z, x.z);  u.w = fmaf(a.w, p.w, x.w);
        ((float4*)outU)[tid] = u;
        ((float4*)outS)[tid] = make_float4(safe_log_neg(u.x), safe_log_neg(u.y),
                                           safe_log_neg(u.z), safe_log_neg(u.w));
        return;
    }

    int ft = tid - NV4;
    if (ft >= NF*4) return;
    int f = ft >> 2, q = ft & 3;
    const int rb = q*4;
    float4 a;
    a.x = g_rz[(rb+0)*KSTRIDE + K] / fmaxf(g_dn[(rb+0)*KSTRIDE + K], 1e-30f);
    a.y = g_rz[(rb+1)*KSTRIDE + K] / fmaxf(g_dn[(rb+1)*KSTRIDE + K], 1e-30f);
    a.z = g_rz[(rb+2)*KSTRIDE + K] / fmaxf(g_dn[(rb+2)*KSTRIDE + K], 1e-30f);
    a.w = g_rz[(rb+3)*KSTRIDE + K] / fmaxf(g_dn[(rb+3)*KSTRIDE + K], 1e-30f);

    int vi = F[f*3], vj = F[f*3+1], vk = F[f*3+2];
    float gix = gI[f*3], giy = gI[f*3+1], giz = gI[f*3+2];
    float gjx = gJ[f*3], gjy = gJ[f*3+1], gjz = gJ[f*3+2];
    float gkx = gK[f*3], gky = gK[f*3+1], gkz = gK[f*3+2];

    float4 xI = g_X[vi*4+q], pI = g_P[vi*4+q];
    float4 xJ = g_X[vj*4+q], pJ = g_P[vj*4+q];
    float4 xK = g_X[vk*4+q], pK = g_P[vk*4+q];
    float4 uI, uJ, uK;
    uI.x = fmaf(a.x, pI.x, xI.x); uI.y = fmaf(a.y, pI.y, xI.y);
    uI.z = fmaf(a.z, pI.z, xI.z); uI.w = fmaf(a.w, pI.w, xI.w);
    uJ.x = fmaf(a.x, pJ.x, xJ.x); uJ.y = fmaf(a.y, pJ.y, xJ.y);
    uJ.z = fmaf(a.z, pJ.z, xJ.z); uJ.w = fmaf(a.w, pJ.w, xJ.w);
    uK.x = fmaf(a.x, pK.x, xK.x); uK.y = fmaf(a.y, pK.y, xK.y);
    uK.z = fmaf(a.z, pK.z, xK.z); uK.w = fmaf(a.w, pK.w, xK.w);

    const float ui[4] = {uI.x, uI.y, uI.z, uI.w};
    const float uj[4] = {uJ.x, uJ.y, uJ.z, uJ.w};
    const float uk[4] = {uK.x, uK.y, uK.z, uK.w};
    float* o = outX + f*48 + q*12;
    #pragma unroll
    for (int c = 0; c < 4; c++){
        float gx = ui[c]*gix + uj[c]*gjx + uk[c]*gkx;
        float gy = ui[c]*giy + uj[c]*gjy + uk[c]*gky;
        float gz = ui[c]*giz + uj[c]*gjz + uk[c]*gkz;
        float n = sqrtf(gx*gx + gy*gy + gz*gz);
        n = fmaxf(n, 1e-12f);
        float inv = -1.0f / n;
        o[c*3+0] = gx*inv;
        o[c*3+1] = gy*inv;
        o[c*3+2] = gz*inv;
    }
}

extern "C" void kernel_launch(void* const* d_in, const int* in_sizes, int n_in,
                              void* d_out, int out_size) {
    const int*   F   = (const int*)  d_in[0];
    const int*   row = (const int*)  d_in[1];
    const int*   col = (const int*)  d_in[2];
    const float* val = (const float*)d_in[3];
    const float* M   = (const float*)d_in[4];
    const float* gI  = (const float*)d_in[5];
    const float* gJ  = (const float*)d_in[6];
    const float* gK  = (const float*)d_in[7];
    const float* B   = (const float*)d_in[8];
    const float* tp  = (const float*)d_in[9];
    int nnz = in_sizes[1];

    float* out  = (float*)d_out;
    float* outU = out;
    float* outX = out + NV*16;
    float* outS = out + NV*16 + NF*16*3;

    zero_k   <<<(NV*7)/256, 256>>>();
    scatter_k<<<(nnz + 255)/256, 256>>>(row, col, val, nnz);
    init_k   <<<CGB, CGT>>>(M, B, tp);
    for (int k = 0; k < ITERS; k++){
        cg_k1<<<CGB, CGT>>>(k);
        if (k < ITERS-1) cg_k2<<<CGB, CGT>>>(k);
    }
    finalize_k<<<(NV4 + NF*4 + CGT-1)/CGT, CGT>>>(F, gI, gJ, gK, outU, outX, outS);
}

// round 13
// speedup vs baseline: 1.1263x; 1.1263x over previous
#include <cuda_runtime.h>
#include <math.h>

#define NV    65536
#define ITERS 40
#define NF    130050
#define NBLK  256
#define NTHR  512
#define KST   64          // per-RHS scalar row stride (256B -> independent L2 lines)
#define NSYNC 96

// ---- device scratch (no allocations allowed) ----
__device__ __align__(16) float    g_W[NV*7];        // aggregated COO weights (slot 0 = diag)
__device__ __align__(16) float4   g_Z[NV*4];        // Z = Minv*R  (stencil operand)
__device__ __align__(16) float    g_dn[16*KST];     // denom[rhs][k], strided rows
__device__ __align__(16) float    g_rz[16*KST];     // rz[rhs][k],   strided rows
__device__ unsigned               g_cnt[NSYNC];

// ---------------- helpers ----------------
__device__ __forceinline__ float4 f4mul(float4 a, float4 b){ return make_float4(a.x*b.x,a.y*b.y,a.z*b.z,a.w*b.w); }
__device__ __forceinline__ float4 f4fma(float4 a, float4 b, float4 c){
    return make_float4(fmaf(a.x,b.x,c.x), fmaf(a.y,b.y,c.y), fmaf(a.z,b.z,c.z), fmaf(a.w,b.w,c.w));
}
__device__ __forceinline__ float4 f4fmas(float s, float4 b, float4 c){
    return make_float4(fmaf(s,b.x,c.x), fmaf(s,b.y,c.y), fmaf(s,b.z,c.z), fmaf(s,b.w,c.w));
}
__device__ __forceinline__ float4 f4scale(float s, float4 a){ return make_float4(s*a.x,s*a.y,s*a.z,s*a.w); }

// software grid barrier: per-index monotone counters, zeroed each launch by zero_k
__device__ __forceinline__ void gsync(int idx){
    __syncthreads();
    if (threadIdx.x == 0){
        __threadfence();
        atomicAdd(&g_cnt[idx], 1u);
        while (*(volatile unsigned*)&g_cnt[idx] < (unsigned)NBLK) { }
        __threadfence();
    }
    __syncthreads();
}

__shared__ __align__(16) float sm_red[16][16];
__shared__ __align__(16) float s_num[16];   // staged scalar numerators
__shared__ __align__(16) float s_den[16];   // staged scalar denominators

// Stage 32 scalars (num[rhs] = A[rhs*KST+ka], den[rhs] = Bt[rhs*KST+kb]) into smem.
__device__ __forceinline__ void stage_scalars(const float* A, int ka, const float* Bt, int kb){
    if (threadIdx.x < 32){
        int r = threadIdx.x & 15;
        float v = (threadIdx.x < 16) ? __ldcg(&A[r*KST + ka]) : __ldcg(&Bt[r*KST + kb]);
        if (threadIdx.x < 16) s_num[r] = v; else s_den[r] = v;
    }
    __syncthreads();
}

// Block reduce: each thread holds 8 partials (s[0..1]) for RHS range h*8..h*8+7,
// h == (lane & 1). Accumulate into base[rhs*KST + k] with atomics (16 separate lines).
__device__ __forceinline__ void reduce16(float4* s, float* base, int k){
    #pragma unroll
    for (int m = 2; m < 32; m <<= 1){
        #pragma unroll
        for (int j = 0; j < 2; j++){
            s[j].x += __shfl_xor_sync(0xffffffffu, s[j].x, m);
            s[j].y += __shfl_xor_sync(0xffffffffu, s[j].y, m);
            s[j].z += __shfl_xor_sync(0xffffffffu, s[j].z, m);
            s[j].w += __shfl_xor_sync(0xffffffffu, s[j].w, m);
        }
    }
    int lane = threadIdx.x & 31, wid = threadIdx.x >> 5;
    if (lane < 2){                       // lane0 -> RHS 0..7, lane1 -> RHS 8..15
        float* row = &sm_red[wid][lane*8];
        row[0] = s[0].x; row[1] = s[0].y; row[2] = s[0].z; row[3] = s[0].w;
        row[4] = s[1].x; row[5] = s[1].y; row[6] = s[1].z; row[7] = s[1].w;
    }
    __syncthreads();
    if (threadIdx.x < 16){
        float acc = 0.f;
        #pragma unroll
        for (int w = 0; w < 16; w++) acc += sm_red[w][threadIdx.x];
        atomicAdd(&base[threadIdx.x*KST + k], acc);
    }
}

// ---------------- setup kernels ----------------
__global__ void zero_k(){
    int tid = blockIdx.x * blockDim.x + threadIdx.x;   // grid sized to exactly NV*7
    g_W[tid] = 0.f;
    if (tid < 16*KST){ g_dn[tid] = 0.f; g_rz[tid] = 0.f; }
    if (tid < NSYNC)   g_cnt[tid] = 0u;
}

__global__ void scatter_k(const int* __restrict__ row, const int* __restrict__ col,
                          const float* __restrict__ val, int nnz){
    int e = blockIdx.x * blockDim.x + threadIdx.x;
    if (e >= nnz) return;
    int r = row[e];
    int d = col[e] - r;
    int slot;
    if      (d == 0)    slot = 0;
    else if (d == -256) slot = 1;
    else if (d == 256)  slot = 2;
    else if (d == -1)   slot = 3;
    else if (d == 1)    slot = 4;
    else if (d == -257) slot = 5;
    else if (d == 257)  slot = 6;
    else return;
    atomicAdd(&g_W[r*7 + slot], val[e]);
}

__device__ __forceinline__ float safe_log_neg(float u){
    float us = u;
    if (isnan(us))      us = 1e-9f;
    else if (isinf(us)) us = (us > 0.f) ? 1.0f : 0.0f;
    return -logf(fmaxf(us, 1e-9f));
}

// ---------------- persistent CG + post ----------------
// 2 threads per vertex: h = tid&1 owns RHS [h*8, h*8+8)
__global__ void __launch_bounds__(NTHR, 2)
cg_persist(const float* __restrict__ M, const float* __restrict__ B,
           const float* __restrict__ tp,
           const int* __restrict__ F, const float* __restrict__ gI,
           const float* __restrict__ gJ, const float* __restrict__ gK,
           float* __restrict__ outU, float* __restrict__ outX, float* __restrict__ outS)
{
    const int gtid = blockIdx.x * NTHR + threadIdx.x;  // [0, NV*2)
    const int v = gtid >> 1;
    const int h = gtid & 1;
    const int jb = h * 2;                              // float4 index base within [0,4)
    const float t = *tp;

    float Dw = M[v] + t * g_W[v*7];
    float Minv = 1.0f / fmaxf(Dw, 1e-12f);
    float offW[6];
    #pragma unroll
    for (int e = 0; e < 6; e++) offW[e] = t * g_W[v*7 + 1 + e];

    float4 X[2], R[2], P[2], AP[2], s[2];
    const float4* B4 = (const float4*)B;
    #pragma unroll
    for (int j = 0; j < 2; j++){
        R[j]  = B4[v*4 + jb + j];
        X[j]  = make_float4(0.f,0.f,0.f,0.f);
        float4 z = f4scale(Minv, R[j]);
        __stcg(&g_Z[v*4 + jb + j], z);
        s[j]  = f4mul(R[j], z);
    }
    reduce16(s, g_rz, 0);
    gsync(0);

    const int off[6] = {-256, 256, -1, 1, -257, 257};

    for (int k = 0; k < ITERS; k++){
        // ---- phase 1: P = Z + beta*P ; AP = A*Z + beta*AP ; denom = <P,AP> ----
        {
            float4 z0 = __ldcg(&g_Z[v*4 + jb]);
            float4 z1 = __ldcg(&g_Z[v*4 + jb + 1]);
            if (k == 0){
                AP[0] = f4scale(Dw, z0);  AP[1] = f4scale(Dw, z1);
                P[0]  = z0;               P[1]  = z1;
            } else {
                stage_scalars(g_rz, k, g_rz, k-1);     // num=rz[k], den=rz[k-1]
                const float* nm = &s_num[h*8];
                const float* dn = &s_den[h*8];
                float4 bt0 = make_float4(nm[0]/fmaxf(dn[0],1e-30f), nm[1]/fmaxf(dn[1],1e-30f),
                                         nm[2]/fmaxf(dn[2],1e-30f), nm[3]/fmaxf(dn[3],1e-30f));
                float4 bt1 = make_float4(nm[4]/fmaxf(dn[4],1e-30f), nm[5]/fmaxf(dn[5],1e-30f),
                                         nm[6]/fmaxf(dn[6],1e-30f), nm[7]/fmaxf(dn[7],1e-30f));
                AP[0] = f4fma(bt0, AP[0], f4scale(Dw, z0));
                AP[1] = f4fma(bt1, AP[1], f4scale(Dw, z1));
                P[0]  = f4fma(bt0, P[0], z0);
                P[1]  = f4fma(bt1, P[1], z1);
            }
        }
        #pragma unroll
        for (int e = 0; e < 6; e++){
            int nb = v + off[e];
            nb = max(0, min(NV-1, nb));      // absent-edge weight is exactly 0
            float w = offW[e];
            float4 z0 = __ldcg(&g_Z[nb*4 + jb]);
            float4 z1 = __ldcg(&g_Z[nb*4 + jb + 1]);
            AP[0] = f4fmas(w, z0, AP[0]);
            AP[1] = f4fmas(w, z1, AP[1]);
        }
        s[0] = f4mul(P[0], AP[0]);
        s[1] = f4mul(P[1], AP[1]);
        reduce16(s, g_dn, k);
        gsync(1 + 2*k);

        // ---- phase 2: alpha ; X += aP ; R -= aAP ; Z = Minv*R ; rz_new = <R,Z> ----
        {
            stage_scalars(g_rz, k, g_dn, k);           // num=rz[k], den=denom[k]
            const float* nm = &s_num[h*8];
            const float* dn = &s_den[h*8];
            float4 a0 = make_float4(nm[0]/fmaxf(dn[0],1e-30f), nm[1]/fmaxf(dn[1],1e-30f),
                                    nm[2]/fmaxf(dn[2],1e-30f), nm[3]/fmaxf(dn[3],1e-30f));
            float4 a1 = make_float4(nm[4]/fmaxf(dn[4],1e-30f), nm[5]/fmaxf(dn[5],1e-30f),
                                    nm[6]/fmaxf(dn[6],1e-30f), nm[7]/fmaxf(dn[7],1e-30f));
            float4 aa[2] = {a0, a1};
            #pragma unroll
            for (int j = 0; j < 2; j++){
                float4 a = aa[j];
                X[j] = f4fma(a, P[j], X[j]);
                float4 na = make_float4(-a.x,-a.y,-a.z,-a.w);
                R[j] = f4fma(na, AP[j], R[j]);
                float4 z = f4scale(Minv, R[j]);
                __stcg(&g_Z[v*4 + jb + j], z);
                s[j] = f4mul(R[j], z);
            }
        }
        reduce16(s, g_rz, k+1);
        gsync(2 + 2*k);
    }

    // ---- write U and S ----
    float4* oU = (float4*)outU;
    float4* oS = (float4*)outS;
    #pragma unroll
    for (int j = 0; j < 2; j++){
        __stcg(&oU[v*4 + jb + j], X[j]);
        oS[v*4 + jb + j] = make_float4(safe_log_neg(X[j].x), safe_log_neg(X[j].y),
                                       safe_log_neg(X[j].z), safe_log_neg(X[j].w));
    }
    gsync(81);

    // ---- faces: Xdir (one face per thread, full 16 RHS) ----
    for (int f = gtid; f < NF; f += NV*2){
        int vi = F[f*3], vj = F[f*3+1], vk = F[f*3+2];
        float gix = gI[f*3], giy = gI[f*3+1], giz = gI[f*3+2];
        float gjx = gJ[f*3], gjy = gJ[f*3+1], gjz = gJ[f*3+2];
        float gkx = gK[f*3], gky = gK[f*3+1], gkz = gK[f*3+2];
        float* o = outX + f*48;
        #pragma unroll
        for (int j = 0; j < 4; j++){
            float4 uI = __ldcg(&oU[vi*4 + j]);
            float4 uJ = __ldcg(&oU[vj*4 + j]);
            float4 uK = __ldcg(&oU[vk*4 + j]);
            const float ui[4] = {uI.x, uI.y, uI.z, uI.w};
            const float uj[4] = {uJ.x, uJ.y, uJ.z, uJ.w};
            const float uk[4] = {uK.x, uK.y, uK.z, uK.w};
            #pragma unroll
            for (int c = 0; c < 4; c++){
                float gx = ui[c]*gix + uj[c]*gjx + uk[c]*gkx;
                float gy = ui[c]*giy + uj[c]*gjy + uk[c]*gky;
                float gz = ui[c]*giz + uj[c]*gjz + uk[c]*gkz;
                float n = sqrtf(gx*gx + gy*gy + gz*gz);
                n = fmaxf(n, 1e-12f);
                float inv = -1.0f / n;
                int cc = j*4 + c;
                o[cc*3+0] = gx*inv;
                o[cc*3+1] = gy*inv;
                o[cc*3+2] = gz*inv;
            }
        }
    }
}

extern "C" void kernel_launch(void* const* d_in, const int* in_sizes, int n_in,
                              void* d_out, int out_size) {
    const int*   F   = (const int*)  d_in[0];
    const int*   row = (const int*)  d_in[1];
    const int*   col = (const int*)  d_in[2];
    const float* val = (const float*)d_in[3];
    const float* M   = (const float*)d_in[4];
    const float* gI  = (const float*)d_in[5];
    const float* gJ  = (const float*)d_in[6];
    const float* gK  = (const float*)d_in[7];
    const float* B   = (const float*)d_in[8];
    const float* tp  = (const float*)d_in[9];
    int nnz = in_sizes[1];

    float* out  = (float*)d_out;
    float* outU = out;
    float* outX = out + NV*16;
    float* outS = out + NV*16 + NF*16*3;

    zero_k   <<<(NV*7)/256, 256>>>();
    scatter_k<<<(nnz + 255)/256, 256>>>(row, col, val, nnz);
    cg_persist<<<NBLK, NTHR>>>(M, B, tp, F, gI, gJ, gK, outU, outX, outS);
}

// round 14
// speedup vs baseline: 1.2470x; 1.1072x over previous
#include <cuda_runtime.h>
#include <math.h>

#define NV    65536
#define ITERS 40
#define NF    130050
#define NBLK  256          // 16x16 tiles of 16x16 vertices
#define NTHR  512
#define KST   64           // per-RHS scalar row stride
#define NSYNC 96

// ---- device scratch (no allocations allowed) ----
__device__ __align__(16) float    g_W[NV*7];        // aggregated COO weights (slot 0 = diag)
__device__ __align__(16) float4   g_Z[NV*4];        // Z (global copy, for halo exchange)
__device__ __align__(16) float    g_dn[16*KST];     // denom[rhs][k], strided rows
__device__ __align__(16) float    g_rz[16*KST];     // rz[rhs][k],   strided rows
__device__ unsigned               g_cnt[NSYNC];

// ---------------- helpers ----------------
__device__ __forceinline__ float4 f4mul(float4 a, float4 b){ return make_float4(a.x*b.x,a.y*b.y,a.z*b.z,a.w*b.w); }
__device__ __forceinline__ float4 f4fma(float4 a, float4 b, float4 c){
    return make_float4(fmaf(a.x,b.x,c.x), fmaf(a.y,b.y,c.y), fmaf(a.z,b.z,c.z), fmaf(a.w,b.w,c.w));
}
__device__ __forceinline__ float4 f4fmas(float s, float4 b, float4 c){
    return make_float4(fmaf(s,b.x,c.x), fmaf(s,b.y,c.y), fmaf(s,b.z,c.z), fmaf(s,b.w,c.w));
}
__device__ __forceinline__ float4 f4scale(float s, float4 a){ return make_float4(s*a.x,s*a.y,s*a.z,s*a.w); }

// software grid barrier: per-index monotone counters, zeroed each launch by zero_k
__device__ __forceinline__ void gsync(int idx){
    __syncthreads();
    if (threadIdx.x == 0){
        __threadfence();
        atomicAdd(&g_cnt[idx], 1u);
        while (*(volatile unsigned*)&g_cnt[idx] < (unsigned)NBLK) { }
        __threadfence();
    }
    __syncthreads();
}

__shared__ __align__(16) float4 s_Z[18*18*4];   // Z tile with halo: 20736 B
__shared__ __align__(16) float  sm_red[16][16];
__shared__ __align__(16) float  s_num[16];
__shared__ __align__(16) float  s_den[16];

// Stage 32 scalars into smem.
__device__ __forceinline__ void stage_scalars(const float* A, int ka, const float* Bt, int kb){
    if (threadIdx.x < 32){
        int r = threadIdx.x & 15;
        float vv = (threadIdx.x < 16) ? __ldcg(&A[r*KST + ka]) : __ldcg(&Bt[r*KST + kb]);
        if (threadIdx.x < 16) s_num[r] = vv; else s_den[r] = vv;
    }
    __syncthreads();
}

// Block reduce: each thread holds 8 partials (s[0..1]) for RHS range h*8..h*8+7,
// h == (lane & 1). Accumulate into base[rhs*KST + k] with atomics (16 separate lines).
__device__ __forceinline__ void reduce16(float4* s, float* base, int k){
    #pragma unroll
    for (int m = 2; m < 32; m <<= 1){
        #pragma unroll
        for (int j = 0; j < 2; j++){
            s[j].x += __shfl_xor_sync(0xffffffffu, s[j].x, m);
            s[j].y += __shfl_xor_sync(0xffffffffu, s[j].y, m);
            s[j].z += __shfl_xor_sync(0xffffffffu, s[j].z, m);
            s[j].w += __shfl_xor_sync(0xffffffffu, s[j].w, m);
        }
    }
    int lane = threadIdx.x & 31, wid = threadIdx.x >> 5;
    if (lane < 2){
        float* row = &sm_red[wid][lane*8];
        row[0] = s[0].x; row[1] = s[0].y; row[2] = s[0].z; row[3] = s[0].w;
        row[4] = s[1].x; row[5] = s[1].y; row[6] = s[1].z; row[7] = s[1].w;
    }
    __syncthreads();
    if (threadIdx.x < 16){
        float acc = 0.f;
        #pragma unroll
        for (int w = 0; w < 16; w++) acc += sm_red[w][threadIdx.x];
        atomicAdd(&base[threadIdx.x*KST + k], acc);
    }
}

// ---------------- setup kernels ----------------
__global__ void zero_k(){
    int tid = blockIdx.x * blockDim.x + threadIdx.x;   // grid sized to exactly NV*7
    g_W[tid] = 0.f;
    if (tid < 16*KST){ g_dn[tid] = 0.f; g_rz[tid] = 0.f; }
    if (tid < NSYNC)   g_cnt[tid] = 0u;
}

__global__ void scatter_k(const int* __restrict__ row, const int* __restrict__ col,
                          const float* __restrict__ val, int nnz){
    int e = blockIdx.x * blockDim.x + threadIdx.x;
    if (e >= nnz) return;
    int r = row[e];
    int d = col[e] - r;
    int slot;
    if      (d == 0)    slot = 0;
    else if (d == -256) slot = 1;
    else if (d == 256)  slot = 2;
    else if (d == -1)   slot = 3;
    else if (d == 1)    slot = 4;
    else if (d == -257) slot = 5;
    else if (d == 257)  slot = 6;
    else return;
    atomicAdd(&g_W[r*7 + slot], val[e]);
}

__device__ __forceinline__ float safe_log_neg(float u){
    float us = u;
    if (isnan(us))      us = 1e-9f;
    else if (isinf(us)) us = (us > 0.f) ? 1.0f : 0.0f;
    return -logf(fmaxf(us, 1e-9f));
}

// ---------------- persistent CG + post (2-D tiled) ----------------
// Block = 16x16 vertex tile. 2 threads per vertex: h owns RHS [h*8, h*8+8).
__global__ void __launch_bounds__(NTHR, 2)
cg_persist(const float* __restrict__ M, const float* __restrict__ B,
           const float* __restrict__ tp,
           const int* __restrict__ F, const float* __restrict__ gI,
           const float* __restrict__ gJ, const float* __restrict__ gK,
           float* __restrict__ outU, float* __restrict__ outX, float* __restrict__ outS)
{
    const int tid  = threadIdx.x;
    const int h    = tid & 1;
    const int vloc = tid >> 1;            // 0..255
    const int ix = vloc & 15, iy = vloc >> 4;
    const int bx = blockIdx.x & 15, by = blockIdx.x >> 4;
    const int gxp = bx*16 + ix, gyp = by*16 + iy;
    const int v  = gyp*256 + gxp;
    const int jb = h * 2;
    const int c0 = ((iy+1)*18 + (ix+1)) * 4;       // own cell float4 base
    const int gtid = blockIdx.x * NTHR + tid;
    const float t = *tp;

    float Dw = M[v] + t * g_W[v*7];
    float Minv = 1.0f / fmaxf(Dw, 1e-12f);
    float offW[6];
    #pragma unroll
    for (int e = 0; e < 6; e++) offW[e] = t * g_W[v*7 + 1 + e];
    // smem float4 deltas matching slot order {-256,+256,-1,+1,-257,+257}
    const int sd[6] = {-72, 72, -4, 4, -76, 76};

    float4 X[2], R[2], P[2], AP[2], Zo[2], s[2];
    const float4* B4 = (const float4*)B;
    #pragma unroll
    for (int j = 0; j < 2; j++){
        R[j]  = B4[v*4 + jb + j];
        X[j]  = make_float4(0.f,0.f,0.f,0.f);
        Zo[j] = f4scale(Minv, R[j]);
        __stcg(&g_Z[v*4 + jb + j], Zo[j]);          // global (halo source)
        s_Z[c0 + jb + j] = Zo[j];                   // smem interior
        s[j]  = f4mul(R[j], Zo[j]);
    }
    reduce16(s, g_rz, 0);
    gsync(0);

    for (int k = 0; k < ITERS; k++){
        // ---- load halo ring (68 cells x 4 float4 = 272 loads, tid<272) ----
        if (tid < 272){
            int cell = tid >> 2, part = tid & 3;
            int cy, cx;
            if      (cell < 18){ cy = 0;        cx = cell; }
            else if (cell < 36){ cy = 17;       cx = cell - 18; }
            else if (cell < 52){ cy = cell - 35; cx = 0; }
            else               { cy = cell - 51; cx = 17; }
            int gyy = min(255, max(0, by*16 + cy - 1));
            int gxx = min(255, max(0, bx*16 + cx - 1));
            s_Z[(cy*18 + cx)*4 + part] = __ldcg(&g_Z[(gyy*256 + gxx)*4 + part]);
        }

        // ---- phase 1: P = Z + beta*P ; AP = A*Z + beta*AP ; denom = <P,AP> ----
        if (k == 0){
            AP[0] = f4scale(Dw, Zo[0]);  AP[1] = f4scale(Dw, Zo[1]);
            P[0]  = Zo[0];               P[1]  = Zo[1];
            __syncthreads();                       // ring visible
        } else {
            stage_scalars(g_rz, k, g_rz, k-1);     // includes __syncthreads (ring visible)
            const float* nm = &s_num[h*8];
            const float* dn = &s_den[h*8];
            float4 bt0 = make_float4(nm[0]/fmaxf(dn[0],1e-30f), nm[1]/fmaxf(dn[1],1e-30f),
                                     nm[2]/fmaxf(dn[2],1e-30f), nm[3]/fmaxf(dn[3],1e-30f));
            float4 bt1 = make_float4(nm[4]/fmaxf(dn[4],1e-30f), nm[5]/fmaxf(dn[5],1e-30f),
                                     nm[6]/fmaxf(dn[6],1e-30f), nm[7]/fmaxf(dn[7],1e-30f));
            AP[0] = f4fma(bt0, AP[0], f4scale(Dw, Zo[0]));
            AP[1] = f4fma(bt1, AP[1], f4scale(Dw, Zo[1]));
            P[0]  = f4fma(bt0, P[0], Zo[0]);
            P[1]  = f4fma(bt1, P[1], Zo[1]);
        }
        #pragma unroll
        for (int e = 0; e < 6; e++){
            float w = offW[e];
            float4 z0 = s_Z[c0 + sd[e] + jb];
            float4 z1 = s_Z[c0 + sd[e] + jb + 1];
            AP[0] = f4fmas(w, z0, AP[0]);
            AP[1] = f4fmas(w, z1, AP[1]);
        }
        s[0] = f4mul(P[0], AP[0]);
        s[1] = f4mul(P[1], AP[1]);
        reduce16(s, g_dn, k);
        gsync(1 + 2*k);

        // ---- phase 2: alpha ; X += aP ; R -= aAP ; Z = Minv*R ; rz_new = <R,Z> ----
        {
            stage_scalars(g_rz, k, g_dn, k);       // num=rz[k], den=denom[k]
            const float* nm = &s_num[h*8];
            const float* dn = &s_den[h*8];
            float4 a0 = make_float4(nm[0]/fmaxf(dn[0],1e-30f), nm[1]/fmaxf(dn[1],1e-30f),
                                    nm[2]/fmaxf(dn[2],1e-30f), nm[3]/fmaxf(dn[3],1e-30f));
            float4 a1 = make_float4(nm[4]/fmaxf(dn[4],1e-30f), nm[5]/fmaxf(dn[5],1e-30f),
                                    nm[6]/fmaxf(dn[6],1e-30f), nm[7]/fmaxf(dn[7],1e-30f));
            float4 aa[2] = {a0, a1};
            #pragma unroll
            for (int j = 0; j < 2; j++){
                float4 a = aa[j];
                X[j] = f4fma(a, P[j], X[j]);
                float4 na = make_float4(-a.x,-a.y,-a.z,-a.w);
                R[j] = f4fma(na, AP[j], R[j]);
                Zo[j] = f4scale(Minv, R[j]);
                __stcg(&g_Z[v*4 + jb + j], Zo[j]);  // global (halo source)
                s_Z[c0 + jb + j] = Zo[j];           // smem interior
                s[j] = f4mul(R[j], Zo[j]);
            }
        }
        reduce16(s, g_rz, k+1);
        gsync(2 + 2*k);
    }

    // ---- write U and S ----
    float4* oU = (float4*)outU;
    float4* oS = (float4*)outS;
    #pragma unroll
    for (int j = 0; j < 2; j++){
        __stcg(&oU[v*4 + jb + j], X[j]);
        oS[v*4 + jb + j] = make_float4(safe_log_neg(X[j].x), safe_log_neg(X[j].y),
                                       safe_log_neg(X[j].z), safe_log_neg(X[j].w));
    }
    gsync(81);

    // ---- faces: Xdir (one face per thread, full 16 RHS) ----
    for (int f = gtid; f < NF; f += NV*2){
        int vi = F[f*3], vj = F[f*3+1], vk = F[f*3+2];
        float gix = gI[f*3], giy = gI[f*3+1], giz = gI[f*3+2];
        float gjx = gJ[f*3], gjy = gJ[f*3+1], gjz = gJ[f*3+2];
        float gkx = gK[f*3], gky = gK[f*3+1], gkz = gK[f*3+2];
        float* o = outX + f*48;
        #pragma unroll
        for (int j = 0; j < 4; j++){
            float4 uI = __ldcg(&oU[vi*4 + j]);
            float4 uJ = __ldcg(&oU[vj*4 + j]);
            float4 uK = __ldcg(&oU[vk*4 + j]);
            const float ui[4] = {uI.x, uI.y, uI.z, uI.w};
            const float uj[4] = {uJ.x, uJ.y, uJ.z, uJ.w};
            const float uk[4] = {uK.x, uK.y, uK.z, uK.w};
            #pragma unroll
            for (int c = 0; c < 4; c++){
                float gx = ui[c]*gix + uj[c]*gjx + uk[c]*gkx;
                float gy = ui[c]*giy + uj[c]*gjy + uk[c]*gky;
                float gz = ui[c]*giz + uj[c]*gjz + uk[c]*gkz;
                float n = sqrtf(gx*gx + gy*gy + gz*gz);
                n = fmaxf(n, 1e-12f);
                float inv = -1.0f / n;
                int cc = j*4 + c;
                o[cc*3+0] = gx*inv;
                o[cc*3+1] = gy*inv;
                o[cc*3+2] = gz*inv;
            }
        }
    }
}

extern "C" void kernel_launch(void* const* d_in, const int* in_sizes, int n_in,
                              void* d_out, int out_size) {
    const int*   F   = (const int*)  d_in[0];
    const int*   row = (const int*)  d_in[1];
    const int*   col = (const int*)  d_in[2];
    const float* val = (const float*)d_in[3];
    const float* M   = (const float*)d_in[4];
    const float* gI  = (const float*)d_in[5];
    const float* gJ  = (const float*)d_in[6];
    const float* gK  = (const float*)d_in[7];
    const float* B   = (const float*)d_in[8];
    const float* tp  = (const float*)d_in[9];
    int nnz = in_sizes[1];

    float* out  = (float*)d_out;
    float* outU = out;
    float* outX = out + NV*16;
    float* outS = out + NV*16 + NF*16*3;

    zero_k   <<<(NV*7)/256, 256>>>();
    scatter_k<<<(nnz + 255)/256, 256>>>(row, col, val, nnz);
    cg_persist<<<NBLK, NTHR>>>(M, B, tp, F, gI, gJ, gK, outU, outX, outS);
}

// round 15
// speedup vs baseline: 1.3517x; 1.0840x over previous
#include <cuda_runtime.h>
#include <math.h>

#define NV    65536
#define ITERS 40
#define NF    130050
#define NBLK  128          // 16 x 8 tiles of (16 wide x 32 tall) vertices
#define NTHR  1024
#define KST   64           // per-RHS scalar row stride
#define NSYNC 96

// ---- device scratch (no allocations allowed) ----
__device__ __align__(16) float    g_W[NV*7];        // aggregated COO weights (slot 0 = diag)
__device__ __align__(16) float4   g_Z[NV*4];        // Z (global copy, for halo exchange)
__device__ __align__(16) float    g_dn[16*KST];     // denom[rhs][k], strided rows
__device__ __align__(16) float    g_rz[16*KST];     // rz[rhs][k],   strided rows
__device__ unsigned               g_cnt[NSYNC];

// ---------------- helpers ----------------
__device__ __forceinline__ float4 f4mul(float4 a, float4 b){ return make_float4(a.x*b.x,a.y*b.y,a.z*b.z,a.w*b.w); }
__device__ __forceinline__ float4 f4fma(float4 a, float4 b, float4 c){
    return make_float4(fmaf(a.x,b.x,c.x), fmaf(a.y,b.y,c.y), fmaf(a.z,b.z,c.z), fmaf(a.w,b.w,c.w));
}
__device__ __forceinline__ float4 f4fmas(float s, float4 b, float4 c){
    return make_float4(fmaf(s,b.x,c.x), fmaf(s,b.y,c.y), fmaf(s,b.z,c.z), fmaf(s,b.w,c.w));
}
__device__ __forceinline__ float4 f4scale(float s, float4 a){ return make_float4(s*a.x,s*a.y,s*a.z,s*a.w); }

// software grid barrier: per-index monotone counters, zeroed each launch by zero_k
__device__ __forceinline__ void gsync(int idx){
    __syncthreads();
    if (threadIdx.x == 0){
        __threadfence();
        atomicAdd(&g_cnt[idx], 1u);
        while (*(volatile unsigned*)&g_cnt[idx] < (unsigned)NBLK) { }
        __threadfence();
    }
    __syncthreads();
}

__shared__ __align__(16) float4 s_Z[34*18*4];   // Z tile with halo: 39168 B
__shared__ __align__(16) float  sm_red[32][16];
__shared__ __align__(16) float  s_rat[16];      // block-uniform alpha/beta ratios

// Compute 16 ratios num[r*KST+ka]/max(den[r*KST+kb],1e-30) once per block.
// Bit-identical to per-thread division (same operands, same op).
__device__ __forceinline__ void stage_ratio(const float* numA, int ka, const float* denA, int kb){
    if (threadIdx.x < 16){
        int r = threadIdx.x;
        float nu = __ldcg(&numA[r*KST + ka]);
        float de = __ldcg(&denA[r*KST + kb]);
        s_rat[r] = nu / fmaxf(de, 1e-30f);
    }
    __syncthreads();
}

// Block reduce: each thread holds 8 partials (s[0..1]) for RHS range h*8..h*8+7,
// h == (lane & 1). Accumulate into base[rhs*KST + k] with atomics (16 separate lines).
__device__ __forceinline__ void reduce16(float4* s, float* base, int k){
    #pragma unroll
    for (int m = 2; m < 32; m <<= 1){
        #pragma unroll
        for (int j = 0; j < 2; j++){
            s[j].x += __shfl_xor_sync(0xffffffffu, s[j].x, m);
            s[j].y += __shfl_xor_sync(0xffffffffu, s[j].y, m);
            s[j].z += __shfl_xor_sync(0xffffffffu, s[j].z, m);
            s[j].w += __shfl_xor_sync(0xffffffffu, s[j].w, m);
        }
    }
    int lane = threadIdx.x & 31, wid = threadIdx.x >> 5;
    if (lane < 2){
        float* row = &sm_red[wid][lane*8];
        row[0] = s[0].x; row[1] = s[0].y; row[2] = s[0].z; row[3] = s[0].w;
        row[4] = s[1].x; row[5] = s[1].y; row[6] = s[1].z; row[7] = s[1].w;
    }
    __syncthreads();
    if (threadIdx.x < 16){
        float acc = 0.f;
        #pragma unroll
        for (int w = 0; w < 32; w++) acc += sm_red[w][threadIdx.x];
        atomicAdd(&base[threadIdx.x*KST + k], acc);
    }
}

// ---------------- setup kernels ----------------
__global__ void zero_k(){
    int tid = blockIdx.x * blockDim.x + threadIdx.x;   // grid sized to exactly NV*7
    g_W[tid] = 0.f;
    if (tid < 16*KST){ g_dn[tid] = 0.f; g_rz[tid] = 0.f; }
    if (tid < NSYNC)   g_cnt[tid] = 0u;
}

__global__ void scatter_k(const int* __restrict__ row, const int* __restrict__ col,
                          const float* __restrict__ val, int nnz){
    int e = blockIdx.x * blockDim.x + threadIdx.x;
    if (e >= nnz) return;
    int r = row[e];
    int d = col[e] - r;
    int slot;
    if      (d == 0)    slot = 0;
    else if (d == -256) slot = 1;
    else if (d == 256)  slot = 2;
    else if (d == -1)   slot = 3;
    else if (d == 1)    slot = 4;
    else if (d == -257) slot = 5;
    else if (d == 257)  slot = 6;
    else return;
    atomicAdd(&g_W[r*7 + slot], val[e]);
}

__device__ __forceinline__ float safe_log_neg(float u){
    float us = u;
    if (isnan(us))      us = 1e-9f;
    else if (isinf(us)) us = (us > 0.f) ? 1.0f : 0.0f;
    return -logf(fmaxf(us, 1e-9f));
}

// ---------------- persistent CG + post (2-D tiled, 16x32 per block) ----------------
__global__ void __launch_bounds__(NTHR, 1)
cg_persist(const float* __restrict__ M, const float* __restrict__ B,
           const float* __restrict__ tp,
           const int* __restrict__ F, const float* __restrict__ gI,
           const float* __restrict__ gJ, const float* __restrict__ gK,
           float* __restrict__ outU, float* __restrict__ outX, float* __restrict__ outS)
{
    const int tid  = threadIdx.x;
    const int h    = tid & 1;
    const int vloc = tid >> 1;            // 0..511
    const int ix = vloc & 15, iy = vloc >> 4;          // ix 0..15, iy 0..31
    const int bx = blockIdx.x & 15, by = blockIdx.x >> 4;  // bx 0..15, by 0..7
    const int gxp = bx*16 + ix, gyp = by*32 + iy;
    const int v  = gyp*256 + gxp;
    const int jb = h * 2;
    const int c0 = ((iy+1)*18 + (ix+1)) * 4;       // own cell float4 base
    const int gtid = blockIdx.x * NTHR + tid;
    const float t = *tp;

    float Dw = M[v] + t * g_W[v*7];
    float Minv = 1.0f / fmaxf(Dw, 1e-12f);
    float offW[6];
    #pragma unroll
    for (int e = 0; e < 6; e++) offW[e] = t * g_W[v*7 + 1 + e];
    // smem float4 deltas matching slot order {-256,+256,-1,+1,-257,+257}
    const int sd[6] = {-72, 72, -4, 4, -76, 76};

    float4 X[2], R[2], P[2], AP[2], Zo[2], s[2];
    const float4* B4 = (const float4*)B;
    #pragma unroll
    for (int j = 0; j < 2; j++){
        R[j]  = B4[v*4 + jb + j];
        X[j]  = make_float4(0.f,0.f,0.f,0.f);
        Zo[j] = f4scale(Minv, R[j]);
        __stcg(&g_Z[v*4 + jb + j], Zo[j]);          // global (halo source)
        s_Z[c0 + jb + j] = Zo[j];                   // smem interior
        s[j]  = f4mul(R[j], Zo[j]);
    }
    reduce16(s, g_rz, 0);
    gsync(0);

    for (int k = 0; k < ITERS; k++){
        // ---- load halo ring (100 cells x 4 float4 = 400 loads, tid<400) ----
        if (tid < 400){
            int cell = tid >> 2, part = tid & 3;
            int cy, cx;
            if      (cell < 18){ cy = 0;        cx = cell; }
            else if (cell < 36){ cy = 33;       cx = cell - 18; }
            else if (cell < 68){ cy = cell - 35; cx = 0; }
            else               { cy = cell - 67; cx = 17; }
            int gyy = min(255, max(0, by*32 + cy - 1));
            int gxx = min(255, max(0, bx*16 + cx - 1));
            s_Z[(cy*18 + cx)*4 + part] = __ldcg(&g_Z[(gyy*256 + gxx)*4 + part]);
        }

        // ---- phase 1: P = Z + beta*P ; AP = A*Z + beta*AP ; denom = <P,AP> ----
        if (k == 0){
            AP[0] = f4scale(Dw, Zo[0]);  AP[1] = f4scale(Dw, Zo[1]);
            P[0]  = Zo[0];               P[1]  = Zo[1];
            __syncthreads();                       // ring visible
        } else {
            stage_ratio(g_rz, k, g_rz, k-1);       // betas; __syncthreads covers ring too
            const float* bt = &s_rat[h*8];
            float4 bt0 = make_float4(bt[0], bt[1], bt[2], bt[3]);
            float4 bt1 = make_float4(bt[4], bt[5], bt[6], bt[7]);
            AP[0] = f4fma(bt0, AP[0], f4scale(Dw, Zo[0]));
            AP[1] = f4fma(bt1, AP[1], f4scale(Dw, Zo[1]));
            P[0]  = f4fma(bt0, P[0], Zo[0]);
            P[1]  = f4fma(bt1, P[1], Zo[1]);
        }
        #pragma unroll
        for (int e = 0; e < 6; e++){
            float w = offW[e];
            float4 z0 = s_Z[c0 + sd[e] + jb];
            float4 z1 = s_Z[c0 + sd[e] + jb + 1];
            AP[0] = f4fmas(w, z0, AP[0]);
            AP[1] = f4fmas(w, z1, AP[1]);
        }
        s[0] = f4mul(P[0], AP[0]);
        s[1] = f4mul(P[1], AP[1]);
        reduce16(s, g_dn, k);
        gsync(1 + 2*k);

        if (k == ITERS-1) break;                   // alpha_39 applied below

        // ---- phase 2: alpha ; X += aP ; R -= aAP ; Z = Minv*R ; rz_new = <R,Z> ----
        {
            stage_ratio(g_rz, k, g_dn, k);         // alphas
            const float* ar = &s_rat[h*8];
            float4 a0 = make_float4(ar[0], ar[1], ar[2], ar[3]);
            float4 a1 = make_float4(ar[4], ar[5], ar[6], ar[7]);
            float4 aa[2] = {a0, a1};
            #pragma unroll
            for (int j = 0; j < 2; j++){
                float4 a = aa[j];
                X[j] = f4fma(a, P[j], X[j]);
                float4 na = make_float4(-a.x,-a.y,-a.z,-a.w);
                R[j] = f4fma(na, AP[j], R[j]);
                Zo[j] = f4scale(Minv, R[j]);
                __stcg(&g_Z[v*4 + jb + j], Zo[j]);  // global (halo source)
                s_Z[c0 + jb + j] = Zo[j];           // smem interior
                s[j] = f4mul(R[j], Zo[j]);
            }
        }
        reduce16(s, g_rz, k+1);
        gsync(2 + 2*k);
    }

    // ---- final: apply alpha_39, write U and S ----
    {
        stage_ratio(g_rz, ITERS-1, g_dn, ITERS-1);
        const float* ar = &s_rat[h*8];
        float4 a0 = make_float4(ar[0], ar[1], ar[2], ar[3]);
        float4 a1 = make_float4(ar[4], ar[5], ar[6], ar[7]);
        float4 aa[2] = {a0, a1};
        float4* oU = (float4*)outU;
        float4* oS = (float4*)outS;
        #pragma unroll
        for (int j = 0; j < 2; j++){
            float4 u = f4fma(aa[j], P[j], X[j]);
            __stcg(&oU[v*4 + jb + j], u);
            oS[v*4 + jb + j] = make_float4(safe_log_neg(u.x), safe_log_neg(u.y),
                                           safe_log_neg(u.z), safe_log_neg(u.w));
        }
    }
    gsync(80);

    // ---- faces: Xdir (one face per thread, full 16 RHS) ----
    const float4* oU = (const float4*)outU;
    for (int f = gtid; f < NF; f += NBLK*NTHR){
        int vi = F[f*3], vj = F[f*3+1], vk = F[f*3+2];
        float gix = gI[f*3], giy = gI[f*3+1], giz = gI[f*3+2];
        float gjx = gJ[f*3], gjy = gJ[f*3+1], gjz = gJ[f*3+2];
        float gkx = gK[f*3], gky = gK[f*3+1], gkz = gK[f*3+2];
        float* o = outX + f*48;
        #pragma unroll
        for (int j = 0; j < 4; j++){
            float4 uI = __ldcg(&oU[vi*4 + j]);
            float4 uJ = __ldcg(&oU[vj*4 + j]);
            float4 uK = __ldcg(&oU[vk*4 + j]);
            const float ui[4] = {uI.x, uI.y, uI.z, uI.w};
            const float uj[4] = {uJ.x, uJ.y, uJ.z, uJ.w};
            const float uk[4] = {uK.x, uK.y, uK.z, uK.w};
            #pragma unroll
            for (int c = 0; c < 4; c++){
                float gx = ui[c]*gix + uj[c]*gjx + uk[c]*gkx;
                float gy = ui[c]*giy + uj[c]*gjy + uk[c]*gky;
                float gz = ui[c]*giz + uj[c]*gjz + uk[c]*gkz;
                float n = sqrtf(gx*gx + gy*gy + gz*gz);
                n = fmaxf(n, 1e-12f);
                float inv = -1.0f / n;
                int cc = j*4 + c;
                o[cc*3+0] = gx*inv;
                o[cc*3+1] = gy*inv;
                o[cc*3+2] = gz*inv;
            }
        }
    }
}

extern "C" void kernel_launch(void* const* d_in, const int* in_sizes, int n_in,
                              void* d_out, int out_size) {
    const int*   F   = (const int*)  d_in[0];
    const int*   row = (const int*)  d_in[1];
    const int*   col = (const int*)  d_in[2];
    const float* val = (const float*)d_in[3];
    const float* M   = (const float*)d_in[4];
    const float* gI  = (const float*)d_in[5];
    const float* gJ  = (const float*)d_in[6];
    const float* gK  = (const float*)d_in[7];
    const float* B   = (const float*)d_in[8];
    const float* tp  = (const float*)d_in[9];
    int nnz = in_sizes[1];

    float* out  = (float*)d_out;
    float* outU = out;
    float* outX = out + NV*16;
    float* outS = out + NV*16 + NF*16*3;

    zero_k   <<<(NV*7)/256, 256>>>();
    scatter_k<<<(nnz + 255)/256, 256>>>(row, col, val, nnz);
    cg_persist<<<NBLK, NTHR>>>(M, B, tp, F, gI, gJ, gK, outU, outX, outS);
}